// round 15
// baseline (speedup 1.0000x reference)
#include <cuda_runtime.h>
#include <math.h>

#define NB 64
#define HWp 484
#define NIMG (NB*HWp)
#define PW 24
#define PSZ 576
#define NS 64

typedef unsigned long long u64;

__device__ float g_z[(size_t)NIMG*HWp];
__device__ float g_z2[(size_t)NIMG*HWp];
__device__ float g_prop[NB*8*HWp];
__device__ float g_conf[NB*HWp];
__device__ float g_fused[NB*HWp];
__device__ float g_r1[(size_t)NB*64*HWp];
__device__ float g_r2[(size_t)NB*32*HWp];
__device__ float g_st[4][16*NS];
__device__ float g_sc[4][8], g_sh[4][8];
__device__ float g_pool[NB*2];

__device__ __forceinline__ float wsum(float v){
#pragma unroll
  for(int o=16;o;o>>=1) v+=__shfl_xor_sync(~0u,v,o);
  return v;
}
__device__ __forceinline__ float wmax(float v){
#pragma unroll
  for(int o=16;o;o>>=1) v=fmaxf(v,__shfl_xor_sync(~0u,v,o));
  return v;
}

// ---- f32x2 packed helpers ----
__device__ __forceinline__ u64 pk2(float lo,float hi){
  u64 r; asm("mov.b64 %0,{%1,%2};":"=l"(r):"f"(lo),"f"(hi)); return r;
}
__device__ __forceinline__ void up2(u64 v,float&a,float&b){
  asm("mov.b64 {%0,%1},%2;":"=f"(a),"=f"(b):"l"(v));
}
__device__ __forceinline__ void fma2(u64&d,u64 a,u64 b){
  asm("fma.rn.f32x2 %0,%1,%2,%0;":"+l"(d):"l"(a),"l"(b));
}

// 3-row patch pairs: P[dy*3+pos], pos pairs (v0,v1)(v1,v2)(v2,v3); cp even
__device__ __forceinline__ void ldpp3(const float* __restrict__ s,int r,int cp,u64 P[9]){
#pragma unroll
  for(int dy=0;dy<3;dy++){
    float2 a=*(const float2*)(s+(r+dy)*PW+cp);
    float2 b=*(const float2*)(s+(r+dy)*PW+cp+2);
    P[dy*3+0]=pk2(a.x,a.y); P[dy*3+1]=pk2(a.y,b.x); P[dy*3+2]=pk2(b.x,b.y);
  }
}
// 4-row patch pairs for 2x2 tiles
__device__ __forceinline__ void ldpp4(const float* __restrict__ s,int r0,int c0,u64 P[12]){
#pragma unroll
  for(int dy=0;dy<4;dy++){
    float2 a=*(const float2*)(s+(r0+dy)*PW+c0);
    float2 b=*(const float2*)(s+(r0+dy)*PW+c0+2);
    P[dy*3+0]=pk2(a.x,a.y); P[dy*3+1]=pk2(a.y,b.x); P[dy*3+2]=pk2(b.x,b.y);
  }
}
// packed 3x3 conv -> (a0,a1); wd = 9 duplicated-weight pairs
__device__ __forceinline__ u64 c3x3p(const u64 P[9],const u64* __restrict__ wd){
  u64 acc=0ull;
#pragma unroll
  for(int k=0;k<9;k++)fma2(acc,P[k],wd[k]);
  return acc;
}
// packed 3x3 conv -> 2x2 (top pair aT, bottom pair aB)
__device__ __forceinline__ void c3x3p4(const u64 P[12],const u64* __restrict__ wd,
    u64&aT,u64&aB){
#pragma unroll
  for(int ky=0;ky<3;ky++)
#pragma unroll
  for(int kx=0;kx<3;kx++){
    fma2(aT,P[ky*3+kx],wd[ky*3+kx]);
    fma2(aB,P[(ky+1)*3+kx],wd[ky*3+kx]);
  }
}

__global__ void zstats_k(){
  int i=blockIdx.x*256+threadIdx.x;
  if(i<4*16*NS)((float*)g_st)[i]=0.f;
}

// conv(1->8) per image, per-channel sum/sumsq (packed 1x2 tiles)
__global__ __launch_bounds__(256) void stats1_k(const float* __restrict__ in,
    const float* __restrict__ w1,int stage){
  __shared__ __align__(16) float sI[PSZ];
  __shared__ __align__(8) float sW2[144];
  __shared__ float sA[16];
  int img=blockIdx.x,t=threadIdx.x;
  const float* src=in+(size_t)img*HWp;
  for(int i=t;i<PSZ;i+=256){int r=i/PW,c=i-r*PW;
    sI[i]=(r>=1&&r<=22&&c>=1&&c<=22)?src[(r-1)*22+c-1]:0.f;}
  if(t<72){float w=w1[t];sW2[2*t]=w;sW2[2*t+1]=w;}
  if(t<16)sA[t]=0.f;
  __syncthreads();
  const u64* wd=(const u64*)sW2;
  float ls[8],lq[8];
#pragma unroll
  for(int o=0;o<8;o++){ls[o]=0.f;lq[o]=0.f;}
  if(t<242){
    int r=t/11,cp=(t-r*11)*2;
    u64 P[9]; ldpp3(sI,r,cp,P);
#pragma unroll
    for(int oc=0;oc<8;oc++){
      u64 acc=c3x3p(P,wd+oc*9);
      float a,b; up2(acc,a,b);
      ls[oc]=a+b; lq[oc]=a*a+b*b;
    }
  }
#pragma unroll
  for(int o=0;o<8;o++){
    float s=wsum(ls[o]),q=wsum(lq[o]);
    if((t&31)==0){atomicAdd(&sA[o],s);atomicAdd(&sA[8+o],q);}}
  __syncthreads();
  if(t<16)atomicAdd(&g_st[stage][t*NS+(img&(NS-1))],sA[t]);
}

__global__ void bnfin_k(int stage,const float* __restrict__ g,
    const float* __restrict__ be,int nch){
  int c=threadIdx.x; if(c>=nch)return;
  float S=0.f,Q=0.f;
  for(int i=0;i<NS;i++){S+=g_st[stage][c*NS+i];Q+=g_st[stage][(8+c)*NS+i];}
  float inv=1.f/((float)NIMG*(float)HWp),m=S*inv,v=fmaxf(Q*inv-m*m,0.f);
  float sc=g[c]*rsqrtf(v+1e-5f);
  g_sc[stage][c]=sc; g_sh[stage][c]=be[c]-m*sc;
}

// conv1(packed 1x2, recompute)+BN+ReLU -> conv2(8->1) packed ic-split 2x2 -> z + stats
__global__ __launch_bounds__(256) void pass2_k(const float* __restrict__ in,
    const float* __restrict__ w1,const float* __restrict__ w2,
    int insel,int bnst,int stst,int zsel){
  __shared__ __align__(16) float sI[PSZ];
  __shared__ __align__(16) float sY[8*PSZ];
  __shared__ __align__(8) float sW2[288];
  __shared__ float sB[16],sA[2];
  __shared__ __align__(16) float zP[484];
  int img=blockIdx.x,t=threadIdx.x;
  const float* src=(insel?(const float*)g_z:in)+(size_t)img*HWp;
  for(int i=t;i<PSZ;i+=256){int r=i/PW,c=i-r*PW;
    sI[i]=(r>=1&&r<=22&&c>=1&&c<=22)?src[(r-1)*22+c-1]:0.f;}
  // zero only sY halo: 92 words/channel
  for(int i=t;i<736;i+=256){
    int ch=i/92,j=i-ch*92,off;
    if(j<24)off=j;
    else if(j<48)off=23*PW+(j-24);
    else if(j<70)off=(j-47)*PW;
    else off=(j-69)*PW+23;
    sY[ch*PSZ+off]=0.f;
  }
  if(t<72){float w=w1[t];sW2[2*t]=w;sW2[2*t+1]=w;
           float v=w2[t];sW2[144+2*t]=v;sW2[145+2*t]=v;}
  if(t<8){sB[t]=g_sc[bnst][t];sB[8+t]=g_sh[bnst][t];}
  if(t<2)sA[t]=0.f;
  __syncthreads();
  const u64* wd1=(const u64*)sW2;
  const u64* wd2=(const u64*)(sW2+144);
  // conv1: 242 threads, packed 1x2 tiles
  if(t<242){
    int r=t/11,cp=(t-r*11)*2;
    u64 P[9]; ldpp3(sI,r,cp,P);
#pragma unroll
    for(int oc=0;oc<8;oc++){
      u64 acc=c3x3p(P,wd1+oc*9);
      float a,b; up2(acc,a,b);
      float sc=sB[oc],sh=sB[8+oc];
      float* yp=sY+oc*PSZ+(r+1)*PW+cp+1;
      yp[0]=fmaxf(fmaf(a,sc,sh),0.f);
      yp[1]=fmaxf(fmaf(b,sc,sh),0.f);
    }
  }
  __syncthreads();
  // conv2: ic-split across block halves, packed 2x2 tiles
  int g=t>>7, idx=t&127;
  bool act=idx<121;
  float z00=0.f,z01=0.f,z10=0.f,z11=0.f;
  int r0=0,c0=0;
  if(act){
    r0=(idx/11)*2; c0=(idx%11)*2;
    u64 aT=0ull,aB=0ull;
#pragma unroll
    for(int ic4=0;ic4<4;ic4++){
      u64 P[12]; ldpp4(sY+(g*4+ic4)*PSZ,r0,c0,P);
      c3x3p4(P,wd2+(g*4+ic4)*9,aT,aB);
    }
    up2(aT,z00,z01); up2(aB,z10,z11);
  }
  if(g==1&&act){
    *(float4*)&zP[idx*4]=make_float4(z00,z01,z10,z11);
  }
  __syncthreads();
  float ls=0.f,lq=0.f;
  if(g==0&&act){
    float4 q=*(const float4*)&zP[idx*4];
    z00+=q.x;z01+=q.y;z10+=q.z;z11+=q.w;
    float* zo=(zsel?g_z2:g_z)+(size_t)img*HWp+r0*22+c0;
    *(float2*)zo=make_float2(z00,z01);
    *(float2*)(zo+22)=make_float2(z10,z11);
    ls=z00+z01+z10+z11;
    lq=z00*z00+z01*z01+z10*z10+z11*z11;
  }
  float s=wsum(ls),q=wsum(lq);
  if((t&31)==0&&t<128){atomicAdd(&sA[0],s);atomicAdd(&sA[1],q);}
  __syncthreads();
  if(t<2)atomicAdd(&g_st[stst][t*8*NS+(img&(NS-1))],sA[t]);
}

// per-image softmax + fused stage-B conv1 stats (packed)
__global__ __launch_bounds__(256) void smaxi_k(const float* __restrict__ w1){
  __shared__ __align__(16) float sP[PSZ];
  __shared__ __align__(8) float sW2[144];
  __shared__ float red[9],sA[16];
  size_t base=(size_t)blockIdx.x*HWp;
  int t=threadIdx.x;
  if(t<92){
    int j=t,off;
    if(j<24)off=j;
    else if(j<48)off=23*PW+(j-24);
    else if(j<70)off=(j-47)*PW;
    else off=(j-69)*PW+23;
    sP[off]=0.f;
  }
  if(t<72){float w=w1[t];sW2[2*t]=w;sW2[2*t+1]=w;}
  if(t<16)sA[t]=0.f;
  float sc=g_sc[1][0];
  float v0=(t<HWp)?g_z[base+t]*sc:-1e30f;
  float v1=(t+256<HWp)?g_z[base+t+256]*sc:-1e30f;
  float m=wmax(fmaxf(v0,v1));
  if((t&31)==0)red[t>>5]=m;
  __syncthreads();
  if(t==0){float x=red[0];for(int i=1;i<8;i++)x=fmaxf(x,red[i]);red[8]=x;}
  __syncthreads();
  m=red[8];
  float e0=(t<HWp)?__expf(v0-m):0.f;
  float e1=(t+256<HWp)?__expf(v1-m):0.f;
  float s=wsum(e0+e1);
  __syncthreads();
  if((t&31)==0)red[t>>5]=s;
  __syncthreads();
  if(t==0){float x=0.f;for(int i=0;i<8;i++)x+=red[i];red[8]=x;}
  __syncthreads();
  float inv=1.f/red[8];
  float p0=e0*inv,p1=e1*inv;
  if(t<HWp){g_z[base+t]=p0;int r=t/22,c=t-r*22;sP[(r+1)*PW+c+1]=p0;}
  if(t+256<HWp){g_z[base+t+256]=p1;int i2=t+256,r=i2/22,c=i2-r*22;sP[(r+1)*PW+c+1]=p1;}
  __syncthreads();
  const u64* wd=(const u64*)sW2;
  float ls[8],lq[8];
#pragma unroll
  for(int o=0;o<8;o++){ls[o]=0.f;lq[o]=0.f;}
  if(t<242){
    int r=t/11,cp=(t-r*11)*2;
    u64 P[9]; ldpp3(sP,r,cp,P);
#pragma unroll
    for(int oc=0;oc<8;oc++){
      u64 acc=c3x3p(P,wd+oc*9);
      float a,b; up2(acc,a,b);
      ls[oc]=a+b; lq[oc]=a*a+b*b;
    }
  }
#pragma unroll
  for(int o=0;o<8;o++){
    float su=wsum(ls[o]),q=wsum(lq[o]);
    if((t&31)==0){atomicAdd(&sA[o],su);atomicAdd(&sA[8+o],q);}}
  __syncthreads();
  if(t<16)atomicAdd(&g_st[2][t*NS+(blockIdx.x&(NS-1))],sA[t]);
}

// two-pass softmax over source positions + conf + einsum prop (coalesced)
__global__ __launch_bounds__(512) void sprop_k(const float* __restrict__ sp){
  __shared__ float sS[HWp*8];
  int n=blockIdx.x,t=threadIdx.x;
  for(int i=t;i<HWp*8;i+=512){int d=i/HWp,p=i-d*HWp;sS[p*8+d]=sp[(n*8+d)*HWp+p];}
  __syncthreads();
  if(t>=HWp)return;
  float sc=g_sc[3][0];
  const float* z=g_z2+(size_t)n*HWp*HWp+t;
  float m=-1e30f;
  for(int p=0;p<HWp;p++)m=fmaxf(m,__ldg(z+(size_t)p*HWp)*sc);
  float s=0.f,acc[8];
#pragma unroll
  for(int d=0;d<8;d++)acc[d]=0.f;
  for(int p=0;p<HWp;p++){
    float e=__expf(__ldg(z+(size_t)p*HWp)*sc-m);
    s+=e;
    const float* st=&sS[p*8];
#pragma unroll
    for(int d=0;d<8;d++)acc[d]=fmaf(e,st[d],acc[d]);
  }
  float inv=1.f/s;
  g_conf[n*HWp+t]=inv;
#pragma unroll
  for(int d=0;d<8;d++)g_prop[(n*8+d)*HWp+t]=acc[d]*inv;
}

// conv 10->64 (+bias,ReLU), 32 oc per block (grid.y=2), packed oc-pairs
__global__ __launch_bounds__(512) void rc1_k(const float* __restrict__ dimp,
    const float* __restrict__ w,const float* __restrict__ b){
  __shared__ float sI[10*PSZ];
  __shared__ __align__(16) float4 sW4[10*9*8];
  int n=blockIdx.x,o0=blockIdx.y*32,t=threadIdx.x;
  for(int i=t;i<10*PSZ;i+=512){
    int ch=i/PSZ,j=i-ch*PSZ,r=j/PW,c=j-r*PW;float val=0.f;
    if(r>=1&&r<=22&&c>=1&&c<=22){int px=(r-1)*22+c-1;
      val=(ch<8)?g_prop[(n*8+ch)*HWp+px]:((ch==8)?dimp[n*HWp+px]:g_conf[n*HWp+px]);}
    sI[i]=val;}
  for(int i=t;i<2880;i+=512)((float*)sW4)[i]=w[(o0+(i&31))*90+(i>>5)];
  __syncthreads();
  if(t>=HWp)return;
  int r=t/22,c=t-r*22;
  u64 A[16];
#pragma unroll
  for(int j=0;j<16;j++)A[j]=pk2(__ldg(&b[o0+2*j]),__ldg(&b[o0+2*j+1]));
  for(int ic=0;ic<10;ic++){
    float v[9];
#pragma unroll
    for(int dy=0;dy<3;dy++)
#pragma unroll
    for(int dx=0;dx<3;dx++)v[dy*3+dx]=sI[ic*PSZ+(r+dy)*PW+c+dx];
#pragma unroll
    for(int k=0;k<9;k++){
      u64 tb=pk2(v[k],v[k]);
#pragma unroll
      for(int o4=0;o4<8;o4++){
        float4 wq=sW4[(ic*9+k)*8+o4];
        fma2(A[o4*2],tb,pk2(wq.x,wq.y));
        fma2(A[o4*2+1],tb,pk2(wq.z,wq.w));
      }
    }
  }
#pragma unroll
  for(int j=0;j<16;j++){
    float a,bb; up2(A[j],a,bb);
    g_r1[((size_t)n*64+o0+2*j)*HWp+t]=fmaxf(a,0.f);
    g_r1[((size_t)n*64+o0+2*j+1)*HWp+t]=fmaxf(bb,0.f);
  }
}

// conv 64->32 (+bias,ReLU), row x oc thread map, 16 oc per block (grid.y=2)
__global__ __launch_bounds__(352) void rc2_k(const float* __restrict__ w,
    const float* __restrict__ b){
  extern __shared__ float sm[];
  float* sW=sm+64*PSZ;
  int n=blockIdx.x,o0=blockIdx.y*16,t=threadIdx.x;
  for(int i=t;i<64*PSZ;i+=352){
    int ch=i/PSZ,j=i-ch*PSZ,r=j/PW,c=j-r*PW;
    sm[i]=(r>=1&&r<=22&&c>=1&&c<=22)?g_r1[((size_t)n*64+ch)*HWp+(r-1)*22+c-1]:0.f;}
  for(int i=t;i<9216;i+=352)sW[i]=w[(o0+(i&15))*576+(i>>4)];
  __syncthreads();
  int row=t>>4,ocl=t&15;
  if(row>=22)return;
  float acc[22];
  float bias=__ldg(&b[o0+ocl]);
#pragma unroll
  for(int c=0;c<22;c++)acc[c]=bias;
  for(int ic=0;ic<64;ic++){
    const float* pb=sm+ic*PSZ+row*PW;
    const float* pw=sW+ic*144+ocl;
#pragma unroll
    for(int dy=0;dy<3;dy++){
      float v[24];
      const float4* q=(const float4*)(pb+dy*PW);
#pragma unroll
      for(int j=0;j<6;j++){float4 f=q[j];v[j*4]=f.x;v[j*4+1]=f.y;v[j*4+2]=f.z;v[j*4+3]=f.w;}
#pragma unroll
      for(int kx=0;kx<3;kx++){
        float wv=pw[(dy*3+kx)*16];
#pragma unroll
        for(int c=0;c<22;c++)acc[c]=fmaf(wv,v[c+kx],acc[c]);}
    }
  }
#pragma unroll
  for(int c=0;c<22;c++)
    g_r2[((size_t)n*32+o0+ocl)*HWp+row*22+c]=fmaxf(acc[c],0.f);
}

// conv 32->1 + sigmoid -> fused (output channel 0)
__global__ __launch_bounds__(512) void rc3_k(const float* __restrict__ w,
    const float* __restrict__ b,float* __restrict__ out){
  extern __shared__ float sm[];
  __shared__ float sW[288];
  int n=blockIdx.x,t=threadIdx.x;
  for(int i=t;i<32*PSZ;i+=512){
    int ch=i/PSZ,j=i-ch*PSZ,r=j/PW,c=j-r*PW;
    sm[i]=(r>=1&&r<=22&&c>=1&&c<=22)?g_r2[((size_t)n*32+ch)*HWp+(r-1)*22+c-1]:0.f;}
  if(t<288)sW[t]=w[t];
  __syncthreads();
  if(t>=HWp)return;
  int r=t/22,c=t-r*22;
  float a=__ldg(&b[0]);
  for(int ic=0;ic<32;ic++)
#pragma unroll
    for(int dy=0;dy<3;dy++)
#pragma unroll
    for(int dx=0;dx<3;dx++)
      a=fmaf(sW[ic*9+dy*3+dx],sm[ic*PSZ+(r+dy)*PW+c+dx],a);
  float f=1.f/(1.f+__expf(-a));
  g_fused[n*HWp+t]=f;
  out[(size_t)n*9*HWp+t]=f;
}

__global__ __launch_bounds__(256) void pool_k(const float* __restrict__ dimp){
  __shared__ float red[16];
  int n=blockIdx.x,t=threadIdx.x;
  float m0=-1e30f,m1=-1e30f;
  for(int i=t;i<HWp;i+=256){
    m0=fmaxf(m0,dimp[n*HWp+i]);
    m1=fmaxf(m1,g_fused[n*HWp+i]);}
  m0=wmax(m0);m1=wmax(m1);
  if((t&31)==0){red[t>>5]=m0;red[8+(t>>5)]=m1;}
  __syncthreads();
  if(t==0){
    float a=red[0],b=red[8];
    for(int i=1;i<8;i++){a=fmaxf(a,red[i]);b=fmaxf(b,red[8+i]);}
    g_pool[n*2]=a;g_pool[n*2+1]=b;}
}

// fused ConvGRU (packed oc-pairs)
__global__ __launch_bounds__(512) void gru_k(const float* __restrict__ dimp,
    const float* __restrict__ rw,const float* __restrict__ rb,
    const float* __restrict__ uw,const float* __restrict__ ub,
    const float* __restrict__ ow,const float* __restrict__ ob,
    float* __restrict__ out){
  __shared__ float sS[12*PSZ];
  __shared__ __align__(16) float sWu[864];
  __shared__ __align__(16) float sWr[864];
  __shared__ __align__(16) float sWo[864];
  int n=blockIdx.x,t=threadIdx.x;
  float p0=g_pool[n*2],p1=g_pool[n*2+1];
  for(int i=t;i<12*PSZ;i+=512){
    int ch=i/PSZ,j=i-ch*PSZ,r=j/PW,c=j-r*PW;float val=0.f;
    if(r>=1&&r<=22&&c>=1&&c<=22){int px=(r-1)*22+c-1;
      val=(ch==0)?dimp[n*HWp+px]:(ch==1)?g_fused[n*HWp+px]:
          (ch==2)?p0:(ch==3)?p1:g_prop[(n*8+ch-4)*HWp+px];}
    sS[i]=val;}
  for(int i=t;i<864;i+=512){
    int oc=i&7,rest=i>>3;
    sWu[i]=uw[oc*108+rest];sWr[i]=rw[oc*108+rest];sWo[i]=ow[oc*108+rest];}
  __syncthreads();
  int r=t/22,c=t-r*22;
  float upd[8],pr[8],rp[8];
  if(t<HWp){
    u64 AU[4],AR[4];
#pragma unroll
    for(int j=0;j<4;j++){
      AU[j]=pk2(__ldg(&ub[2*j]),__ldg(&ub[2*j+1]));
      AR[j]=pk2(__ldg(&rb[2*j]),__ldg(&rb[2*j+1]));
    }
    for(int ic=0;ic<12;ic++)
#pragma unroll
      for(int dy=0;dy<3;dy++)
#pragma unroll
      for(int dx=0;dx<3;dx++){
        float v=sS[ic*PSZ+(r+dy)*PW+c+dx];
        u64 vb=pk2(v,v);
        int k=(ic*9+dy*3+dx)*8;
        const float4* qu=(const float4*)(sWu+k);
        const float4* qr=(const float4*)(sWr+k);
        float4 a=qu[0],bq=qu[1],cq=qr[0],dq=qr[1];
        fma2(AU[0],vb,pk2(a.x,a.y));  fma2(AU[1],vb,pk2(a.z,a.w));
        fma2(AU[2],vb,pk2(bq.x,bq.y));fma2(AU[3],vb,pk2(bq.z,bq.w));
        fma2(AR[0],vb,pk2(cq.x,cq.y));fma2(AR[1],vb,pk2(cq.z,cq.w));
        fma2(AR[2],vb,pk2(dq.x,dq.y));fma2(AR[3],vb,pk2(dq.z,dq.w));
      }
    float au[8],ar[8];
#pragma unroll
    for(int j=0;j<4;j++){up2(AU[j],au[2*j],au[2*j+1]);up2(AR[j],ar[2*j],ar[2*j+1]);}
#pragma unroll
    for(int o=0;o<8;o++){
      upd[o]=1.f/(1.f+__expf(-au[o]));
      float rst=1.f/(1.f+__expf(-ar[o]));
      pr[o]=sS[(4+o)*PSZ+(r+1)*PW+c+1];
      rp[o]=pr[o]*rst;}
  }
  __syncthreads();
  if(t<HWp)
#pragma unroll
    for(int o=0;o<8;o++)sS[(4+o)*PSZ+(r+1)*PW+c+1]=rp[o];
  __syncthreads();
  if(t>=HWp)return;
  u64 AO[4];
#pragma unroll
  for(int j=0;j<4;j++)AO[j]=pk2(__ldg(&ob[2*j]),__ldg(&ob[2*j+1]));
  for(int ic=0;ic<12;ic++)
#pragma unroll
    for(int dy=0;dy<3;dy++)
#pragma unroll
    for(int dx=0;dx<3;dx++){
      float v=sS[ic*PSZ+(r+dy)*PW+c+dx];
      u64 vb=pk2(v,v);
      int k=(ic*9+dy*3+dx)*8;
      const float4* q=(const float4*)(sWo+k);
      float4 a=q[0],bq=q[1];
      fma2(AO[0],vb,pk2(a.x,a.y));  fma2(AO[1],vb,pk2(a.z,a.w));
      fma2(AO[2],vb,pk2(bq.x,bq.y));fma2(AO[3],vb,pk2(bq.z,bq.w));
    }
  float ao[8];
#pragma unroll
  for(int j=0;j<4;j++)up2(AO[j],ao[2*j],ao[2*j+1]);
#pragma unroll
  for(int o=0;o<8;o++){
    float ov=tanhf(ao[o]);
    float sn=pr[o]*(1.f-upd[o])+ov*upd[o];
    out[(size_t)n*9*HWp+(o+1)*HWp+t]=sn;}
}

extern "C" void kernel_launch(void* const* d_in, const int* in_sizes, int n_in,
                              void* d_out, int out_size) {
  const float* cv  =(const float*)d_in[0];
  const float* sp  =(const float*)d_in[1];
  const float* dimp=(const float*)d_in[2];
  float* out=(float*)d_out;
  cudaFuncSetAttribute(rc2_k,cudaFuncAttributeMaxDynamicSharedMemorySize,64*PSZ*4+9216*4);
  cudaFuncSetAttribute(rc3_k,cudaFuncAttributeMaxDynamicSharedMemorySize,32*PSZ*4);

  zstats_k<<<16,256>>>();
  // stage A (cv1)
  stats1_k<<<NIMG,256>>>(cv,(const float*)d_in[3],0);
  bnfin_k<<<1,8>>>(0,(const float*)d_in[5],(const float*)d_in[6],8);
  pass2_k<<<NIMG,256>>>(cv,(const float*)d_in[3],(const float*)d_in[7],0,0,1,0);
  bnfin_k<<<1,8>>>(1,(const float*)d_in[9],(const float*)d_in[10],1);
  // per-image softmax + fused stage-B conv1 stats
  smaxi_k<<<NIMG,256>>>((const float*)d_in[11]);
  bnfin_k<<<1,8>>>(2,(const float*)d_in[13],(const float*)d_in[14],8);
  // stage B (cv2)
  pass2_k<<<NIMG,256>>>(cv,(const float*)d_in[11],(const float*)d_in[15],1,2,3,1);
  bnfin_k<<<1,8>>>(3,(const float*)d_in[17],(const float*)d_in[18],1);
  // softmax over positions + conf + propagation
  sprop_k<<<NB,512>>>(sp);
  // response head
  rc1_k<<<dim3(NB,2),512>>>(dimp,(const float*)d_in[19],(const float*)d_in[20]);
  rc2_k<<<dim3(NB,2),352,64*PSZ*4+9216*4>>>((const float*)d_in[21],(const float*)d_in[22]);
  rc3_k<<<NB,512,32*PSZ*4>>>((const float*)d_in[23],(const float*)d_in[24],out);
  // GRU
  pool_k<<<NB,256>>>(dimp);
  gru_k<<<NB,512>>>(dimp,
    (const float*)d_in[25],(const float*)d_in[26],
    (const float*)d_in[27],(const float*)d_in[28],
    (const float*)d_in[29],(const float*)d_in[30],out);
}

// round 16
// speedup vs baseline: 1.1566x; 1.1566x over previous
#include <cuda_runtime.h>
#include <math.h>

#define NB 64
#define HWp 484
#define NIMG (NB*HWp)
#define PW 24
#define SSZ 600          /* swizzled 24x24 buffer size: SOFF(23)+23 = 586 < 600 */
#define NS 64
/* row-swizzled offset: breaks even-bank pileup (degree 3 -> 2) */
#define SOFF(r) ((r)*PW + ((r)>>1))

__device__ float g_z[(size_t)NIMG*HWp];
__device__ float g_z2[(size_t)NIMG*HWp];
__device__ float g_prop[NB*8*HWp];
__device__ float g_conf[NB*HWp];
__device__ float g_fused[NB*HWp];
__device__ float g_r1[(size_t)NB*64*HWp];
__device__ float g_r2[(size_t)NB*32*HWp];
__device__ float g_st[4][16*NS];
__device__ float g_sc[4][8], g_sh[4][8];
__device__ float g_pool[NB*2];

__device__ __forceinline__ float wsum(float v){
#pragma unroll
  for(int o=16;o;o>>=1) v+=__shfl_xor_sync(~0u,v,o);
  return v;
}
__device__ __forceinline__ float wmax(float v){
#pragma unroll
  for(int o=16;o;o>>=1) v=fmaxf(v,__shfl_xor_sync(~0u,v,o));
  return v;
}

// 3x4 patch (v[dy*4+dx]) at output (r,cp) from swizzled buffer, scalar loads
__device__ __forceinline__ void ldp12s(const float* __restrict__ s,int r,int cp,float v[12]){
#pragma unroll
  for(int dy=0;dy<3;dy++){
    const float* p=s+SOFF(r+dy)+cp;
#pragma unroll
    for(int dx=0;dx<4;dx++)v[dy*4+dx]=p[dx];
  }
}
// 4x4 patch at (r0,c0), scalar loads
__device__ __forceinline__ void ldp16s(const float* __restrict__ s,int r0,int c0,float v[16]){
#pragma unroll
  for(int dy=0;dy<4;dy++){
    const float* p=s+SOFF(r0+dy)+c0;
#pragma unroll
    for(int dx=0;dx<4;dx++)v[dy*4+dx]=p[dx];
  }
}
// 3x3 conv -> 1x2 outputs from 3x4 patch
__device__ __forceinline__ void c3x3_2(const float v[12],const float* __restrict__ w,
    float&a0,float&a1){
#pragma unroll
  for(int ky=0;ky<3;ky++)
#pragma unroll
  for(int kx=0;kx<3;kx++){
    float wv=w[ky*3+kx];
    a0=fmaf(wv,v[ky*4+kx],a0); a1=fmaf(wv,v[ky*4+kx+1],a1);
  }
}
// 3x3 conv -> 2x2 outputs from 4x4 patch
__device__ __forceinline__ void c3x3_4(const float v[16],const float* __restrict__ w,
    float&a00,float&a01,float&a10,float&a11){
#pragma unroll
  for(int ky=0;ky<3;ky++)
#pragma unroll
  for(int kx=0;kx<3;kx++){
    float wv=w[ky*3+kx];
    a00=fmaf(wv,v[ky*4+kx],a00);      a01=fmaf(wv,v[ky*4+kx+1],a01);
    a10=fmaf(wv,v[(ky+1)*4+kx],a10);  a11=fmaf(wv,v[(ky+1)*4+kx+1],a11);
  }
}

__global__ void zstats_k(){
  int i=blockIdx.x*256+threadIdx.x;
  if(i<4*16*NS)((float*)g_st)[i]=0.f;
}

// conv(1->8) per image, per-channel sum/sumsq (1x2 tiles, swizzled sI)
__global__ __launch_bounds__(256) void stats1_k(const float* __restrict__ in,
    const float* __restrict__ w1,int stage){
  __shared__ float sI[SSZ],sW[72],sA[16];
  int img=blockIdx.x,t=threadIdx.x;
  const float* src=in+(size_t)img*HWp;
  for(int i=t;i<576;i+=256){int r=i/PW,c=i-r*PW;
    sI[SOFF(r)+c]=(r>=1&&r<=22&&c>=1&&c<=22)?src[(r-1)*22+c-1]:0.f;}
  if(t<72)sW[t]=w1[t];
  if(t<16)sA[t]=0.f;
  __syncthreads();
  float ls[8],lq[8];
#pragma unroll
  for(int o=0;o<8;o++){ls[o]=0.f;lq[o]=0.f;}
  if(t<242){
    int r=t/11,cp=(t-r*11)*2;
    float v[12]; ldp12s(sI,r,cp,v);
#pragma unroll
    for(int oc=0;oc<8;oc++){
      float a=0.f,b=0.f;
      c3x3_2(v,sW+oc*9,a,b);
      ls[oc]=a+b; lq[oc]=a*a+b*b;
    }
  }
#pragma unroll
  for(int o=0;o<8;o++){
    float s=wsum(ls[o]),q=wsum(lq[o]);
    if((t&31)==0){atomicAdd(&sA[o],s);atomicAdd(&sA[8+o],q);}}
  __syncthreads();
  if(t<16)atomicAdd(&g_st[stage][t*NS+(img&(NS-1))],sA[t]);
}

__global__ void bnfin_k(int stage,const float* __restrict__ g,
    const float* __restrict__ be,int nch){
  int c=threadIdx.x; if(c>=nch)return;
  float S=0.f,Q=0.f;
  for(int i=0;i<NS;i++){S+=g_st[stage][c*NS+i];Q+=g_st[stage][(8+c)*NS+i];}
  float inv=1.f/((float)NIMG*(float)HWp),m=S*inv,v=fmaxf(Q*inv-m*m,0.f);
  float sc=g[c]*rsqrtf(v+1e-5f);
  g_sc[stage][c]=sc; g_sh[stage][c]=be[c]-m*sc;
}

// conv1(1x2, recompute)+BN+ReLU in swizzled SMEM -> conv2(8->1) ic-split 2x2 -> z + stats
__global__ __launch_bounds__(256) void pass2_k(const float* __restrict__ in,
    const float* __restrict__ w1,const float* __restrict__ w2,
    int insel,int bnst,int stst,int zsel){
  __shared__ float sI[SSZ],sY[8*SSZ],sW[144],sB[16],sA[2];
  __shared__ __align__(16) float zP[484];
  int img=blockIdx.x,t=threadIdx.x;
  const float* src=(insel?(const float*)g_z:in)+(size_t)img*HWp;
  for(int i=t;i<576;i+=256){int r=i/PW,c=i-r*PW;
    sI[SOFF(r)+c]=(r>=1&&r<=22&&c>=1&&c<=22)?src[(r-1)*22+c-1]:0.f;}
  // zero only sY halo (rows 0,23; cols 0,23): 92 cells/channel
  for(int i=t;i<736;i+=256){
    int ch=i/92,j=i-ch*92,off;
    if(j<24)off=SOFF(0)+j;
    else if(j<48)off=SOFF(23)+(j-24);
    else if(j<70)off=SOFF(j-47);
    else off=SOFF(j-69)+23;
    sY[ch*SSZ+off]=0.f;
  }
  if(t<72){sW[t]=w1[t];sW[72+t]=w2[t];}
  if(t<8){sB[t]=g_sc[bnst][t];sB[8+t]=g_sh[bnst][t];}
  if(t<2)sA[t]=0.f;
  __syncthreads();
  // conv1: 242 threads, 1x2 tiles
  if(t<242){
    int r=t/11,cp=(t-r*11)*2;
    float v[12]; ldp12s(sI,r,cp,v);
#pragma unroll
    for(int oc=0;oc<8;oc++){
      float a=0.f,b=0.f;
      c3x3_2(v,sW+oc*9,a,b);
      float sc=sB[oc],sh=sB[8+oc];
      float* yp=sY+oc*SSZ+SOFF(r+1)+cp+1;
      yp[0]=fmaxf(fmaf(a,sc,sh),0.f);
      yp[1]=fmaxf(fmaf(b,sc,sh),0.f);
    }
  }
  __syncthreads();
  // conv2: ic-split across block halves, 2x2 tiles
  int g=t>>7, idx=t&127;
  bool act=idx<121;
  float z00=0.f,z01=0.f,z10=0.f,z11=0.f;
  int r0=0,c0=0;
  if(act){
    r0=(idx/11)*2; c0=(idx%11)*2;
#pragma unroll
    for(int ic4=0;ic4<4;ic4++){
      float u[16]; ldp16s(sY+(g*4+ic4)*SSZ,r0,c0,u);
      c3x3_4(u,sW+72+(g*4+ic4)*9,z00,z01,z10,z11);
    }
  }
  if(g==1&&act){
    *(float4*)&zP[idx*4]=make_float4(z00,z01,z10,z11);
  }
  __syncthreads();
  float ls=0.f,lq=0.f;
  if(g==0&&act){
    float4 q=*(const float4*)&zP[idx*4];
    z00+=q.x;z01+=q.y;z10+=q.z;z11+=q.w;
    float* zo=(zsel?g_z2:g_z)+(size_t)img*HWp+r0*22+c0;
    *(float2*)zo=make_float2(z00,z01);
    *(float2*)(zo+22)=make_float2(z10,z11);
    ls=z00+z01+z10+z11;
    lq=z00*z00+z01*z01+z10*z10+z11*z11;
  }
  float s=wsum(ls),q=wsum(lq);
  if((t&31)==0&&t<128){atomicAdd(&sA[0],s);atomicAdd(&sA[1],q);}
  __syncthreads();
  if(t<2)atomicAdd(&g_st[stst][t*8*NS+(img&(NS-1))],sA[t]);
}

// per-image softmax (BN shift cancels; scale applied) + fused stage-B conv1 stats
__global__ __launch_bounds__(256) void smaxi_k(const float* __restrict__ w1){
  __shared__ float sP[SSZ],sW[72],red[9],sA[16];
  size_t base=(size_t)blockIdx.x*HWp;
  int t=threadIdx.x;
  if(t<92){
    int j=t,off;
    if(j<24)off=SOFF(0)+j;
    else if(j<48)off=SOFF(23)+(j-24);
    else if(j<70)off=SOFF(j-47);
    else off=SOFF(j-69)+23;
    sP[off]=0.f;
  }
  if(t<72)sW[t]=w1[t];
  if(t<16)sA[t]=0.f;
  float sc=g_sc[1][0];
  float v0=(t<HWp)?g_z[base+t]*sc:-1e30f;
  float v1=(t+256<HWp)?g_z[base+t+256]*sc:-1e30f;
  float m=wmax(fmaxf(v0,v1));
  if((t&31)==0)red[t>>5]=m;
  __syncthreads();
  if(t==0){float x=red[0];for(int i=1;i<8;i++)x=fmaxf(x,red[i]);red[8]=x;}
  __syncthreads();
  m=red[8];
  float e0=(t<HWp)?__expf(v0-m):0.f;
  float e1=(t+256<HWp)?__expf(v1-m):0.f;
  float s=wsum(e0+e1);
  __syncthreads();
  if((t&31)==0)red[t>>5]=s;
  __syncthreads();
  if(t==0){float x=0.f;for(int i=0;i<8;i++)x+=red[i];red[8]=x;}
  __syncthreads();
  float inv=1.f/red[8];
  float p0=e0*inv,p1=e1*inv;
  if(t<HWp){g_z[base+t]=p0;int r=t/22,c=t-r*22;sP[SOFF(r+1)+c+1]=p0;}
  if(t+256<HWp){g_z[base+t+256]=p1;int i2=t+256,r=i2/22,c=i2-r*22;sP[SOFF(r+1)+c+1]=p1;}
  __syncthreads();
  float ls[8],lq[8];
#pragma unroll
  for(int o=0;o<8;o++){ls[o]=0.f;lq[o]=0.f;}
  if(t<242){
    int r=t/11,cp=(t-r*11)*2;
    float v[12]; ldp12s(sP,r,cp,v);
#pragma unroll
    for(int oc=0;oc<8;oc++){
      float a=0.f,b=0.f;
      c3x3_2(v,sW+oc*9,a,b);
      ls[oc]=a+b; lq[oc]=a*a+b*b;
    }
  }
#pragma unroll
  for(int o=0;o<8;o++){
    float su=wsum(ls[o]),q=wsum(lq[o]);
    if((t&31)==0){atomicAdd(&sA[o],su);atomicAdd(&sA[8+o],q);}}
  __syncthreads();
  if(t<16)atomicAdd(&g_st[2][t*NS+(blockIdx.x&(NS-1))],sA[t]);
}

// two-pass softmax over source positions + conf + einsum prop (coalesced)
__global__ __launch_bounds__(512) void sprop_k(const float* __restrict__ sp){
  __shared__ float sS[HWp*8];
  int n=blockIdx.x,t=threadIdx.x;
  for(int i=t;i<HWp*8;i+=512){int d=i/HWp,p=i-d*HWp;sS[p*8+d]=sp[(n*8+d)*HWp+p];}
  __syncthreads();
  if(t>=HWp)return;
  float sc=g_sc[3][0];
  const float* z=g_z2+(size_t)n*HWp*HWp+t;
  float m=-1e30f;
  for(int p=0;p<HWp;p++)m=fmaxf(m,__ldg(z+(size_t)p*HWp)*sc);
  float s=0.f,acc[8];
#pragma unroll
  for(int d=0;d<8;d++)acc[d]=0.f;
  for(int p=0;p<HWp;p++){
    float e=__expf(__ldg(z+(size_t)p*HWp)*sc-m);
    s+=e;
    const float* st=&sS[p*8];
#pragma unroll
    for(int d=0;d<8;d++)acc[d]=fmaf(e,st[d],acc[d]);
  }
  float inv=1.f/s;
  g_conf[n*HWp+t]=inv;
#pragma unroll
  for(int d=0;d<8;d++)g_prop[(n*8+d)*HWp+t]=acc[d]*inv;
}

// conv 10->64 (+bias,ReLU), 32 oc per block (grid.y=2)
#define PSZ 576
__global__ __launch_bounds__(512) void rc1_k(const float* __restrict__ dimp,
    const float* __restrict__ w,const float* __restrict__ b){
  __shared__ float sI[10*PSZ];
  __shared__ float4 sW4[10*9*8];
  int n=blockIdx.x,o0=blockIdx.y*32,t=threadIdx.x;
  for(int i=t;i<10*PSZ;i+=512){
    int ch=i/PSZ,j=i-ch*PSZ,r=j/PW,c=j-r*PW;float val=0.f;
    if(r>=1&&r<=22&&c>=1&&c<=22){int px=(r-1)*22+c-1;
      val=(ch<8)?g_prop[(n*8+ch)*HWp+px]:((ch==8)?dimp[n*HWp+px]:g_conf[n*HWp+px]);}
    sI[i]=val;}
  for(int i=t;i<2880;i+=512)((float*)sW4)[i]=w[(o0+(i&31))*90+(i>>5)];
  __syncthreads();
  if(t>=HWp)return;
  int r=t/22,c=t-r*22;
  float acc[32];
#pragma unroll
  for(int o=0;o<32;o++)acc[o]=__ldg(&b[o0+o]);
  for(int ic=0;ic<10;ic++){
    float v[9];
#pragma unroll
    for(int dy=0;dy<3;dy++)
#pragma unroll
    for(int dx=0;dx<3;dx++)v[dy*3+dx]=sI[ic*PSZ+(r+dy)*PW+c+dx];
#pragma unroll
    for(int k=0;k<9;k++){
      float tv=v[k];
#pragma unroll
      for(int o4=0;o4<8;o4++){
        float4 wq=sW4[(ic*9+k)*8+o4];
        acc[o4*4+0]=fmaf(tv,wq.x,acc[o4*4+0]);acc[o4*4+1]=fmaf(tv,wq.y,acc[o4*4+1]);
        acc[o4*4+2]=fmaf(tv,wq.z,acc[o4*4+2]);acc[o4*4+3]=fmaf(tv,wq.w,acc[o4*4+3]);}
    }
  }
#pragma unroll
  for(int o=0;o<32;o++)g_r1[((size_t)n*64+o0+o)*HWp+t]=fmaxf(acc[o],0.f);
}

// conv 64->32 (+bias,ReLU), row x oc thread map, 16 oc per block (grid.y=2)
__global__ __launch_bounds__(352) void rc2_k(const float* __restrict__ w,
    const float* __restrict__ b){
  extern __shared__ float sm[];
  float* sW=sm+64*PSZ;
  int n=blockIdx.x,o0=blockIdx.y*16,t=threadIdx.x;
  for(int i=t;i<64*PSZ;i+=352){
    int ch=i/PSZ,j=i-ch*PSZ,r=j/PW,c=j-r*PW;
    sm[i]=(r>=1&&r<=22&&c>=1&&c<=22)?g_r1[((size_t)n*64+ch)*HWp+(r-1)*22+c-1]:0.f;}
  for(int i=t;i<9216;i+=352)sW[i]=w[(o0+(i&15))*576+(i>>4)];
  __syncthreads();
  int row=t>>4,ocl=t&15;
  if(row>=22)return;
  float acc[22];
  float bias=__ldg(&b[o0+ocl]);
#pragma unroll
  for(int c=0;c<22;c++)acc[c]=bias;
  for(int ic=0;ic<64;ic++){
    const float* pb=sm+ic*PSZ+row*PW;
    const float* pw=sW+ic*144+ocl;
#pragma unroll
    for(int dy=0;dy<3;dy++){
      float v[24];
      const float4* q=(const float4*)(pb+dy*PW);
#pragma unroll
      for(int j=0;j<6;j++){float4 f=q[j];v[j*4]=f.x;v[j*4+1]=f.y;v[j*4+2]=f.z;v[j*4+3]=f.w;}
#pragma unroll
      for(int kx=0;kx<3;kx++){
        float wv=pw[(dy*3+kx)*16];
#pragma unroll
        for(int c=0;c<22;c++)acc[c]=fmaf(wv,v[c+kx],acc[c]);}
    }
  }
#pragma unroll
  for(int c=0;c<22;c++)
    g_r2[((size_t)n*32+o0+ocl)*HWp+row*22+c]=fmaxf(acc[c],0.f);
}

// conv 32->1 + sigmoid -> fused (output channel 0)
__global__ __launch_bounds__(512) void rc3_k(const float* __restrict__ w,
    const float* __restrict__ b,float* __restrict__ out){
  extern __shared__ float sm[];
  __shared__ float sW[288];
  int n=blockIdx.x,t=threadIdx.x;
  for(int i=t;i<32*PSZ;i+=512){
    int ch=i/PSZ,j=i-ch*PSZ,r=j/PW,c=j-r*PW;
    sm[i]=(r>=1&&r<=22&&c>=1&&c<=22)?g_r2[((size_t)n*32+ch)*HWp+(r-1)*22+c-1]:0.f;}
  if(t<288)sW[t]=w[t];
  __syncthreads();
  if(t>=HWp)return;
  int r=t/22,c=t-r*22;
  float a=__ldg(&b[0]);
  for(int ic=0;ic<32;ic++)
#pragma unroll
    for(int dy=0;dy<3;dy++)
#pragma unroll
    for(int dx=0;dx<3;dx++)
      a=fmaf(sW[ic*9+dy*3+dx],sm[ic*PSZ+(r+dy)*PW+c+dx],a);
  float f=1.f/(1.f+__expf(-a));
  g_fused[n*HWp+t]=f;
  out[(size_t)n*9*HWp+t]=f;
}

__global__ __launch_bounds__(256) void pool_k(const float* __restrict__ dimp){
  __shared__ float red[16];
  int n=blockIdx.x,t=threadIdx.x;
  float m0=-1e30f,m1=-1e30f;
  for(int i=t;i<HWp;i+=256){
    m0=fmaxf(m0,dimp[n*HWp+i]);
    m1=fmaxf(m1,g_fused[n*HWp+i]);}
  m0=wmax(m0);m1=wmax(m1);
  if((t&31)==0){red[t>>5]=m0;red[8+(t>>5)]=m1;}
  __syncthreads();
  if(t==0){
    float a=red[0],b=red[8];
    for(int i=1;i<8;i++){a=fmaxf(a,red[i]);b=fmaxf(b,red[8+i]);}
    g_pool[n*2]=a;g_pool[n*2+1]=b;}
}

// fused ConvGRU
__global__ __launch_bounds__(512) void gru_k(const float* __restrict__ dimp,
    const float* __restrict__ rw,const float* __restrict__ rb,
    const float* __restrict__ uw,const float* __restrict__ ub,
    const float* __restrict__ ow,const float* __restrict__ ob,
    float* __restrict__ out){
  __shared__ float sS[12*PSZ];
  __shared__ __align__(16) float sWu[864];
  __shared__ __align__(16) float sWr[864];
  __shared__ __align__(16) float sWo[864];
  int n=blockIdx.x,t=threadIdx.x;
  float p0=g_pool[n*2],p1=g_pool[n*2+1];
  for(int i=t;i<12*PSZ;i+=512){
    int ch=i/PSZ,j=i-ch*PSZ,r=j/PW,c=j-r*PW;float val=0.f;
    if(r>=1&&r<=22&&c>=1&&c<=22){int px=(r-1)*22+c-1;
      val=(ch==0)?dimp[n*HWp+px]:(ch==1)?g_fused[n*HWp+px]:
          (ch==2)?p0:(ch==3)?p1:g_prop[(n*8+ch-4)*HWp+px];}
    sS[i]=val;}
  for(int i=t;i<864;i+=512){
    int oc=i&7,rest=i>>3;
    sWu[i]=uw[oc*108+rest];sWr[i]=rw[oc*108+rest];sWo[i]=ow[oc*108+rest];}
  __syncthreads();
  int r=t/22,c=t-r*22;
  float upd[8],pr[8],rp[8];
  if(t<HWp){
    float au[8],ar[8];
#pragma unroll
    for(int o=0;o<8;o++){au[o]=__ldg(&ub[o]);ar[o]=__ldg(&rb[o]);}
    for(int ic=0;ic<12;ic++)
#pragma unroll
      for(int dy=0;dy<3;dy++)
#pragma unroll
      for(int dx=0;dx<3;dx++){
        float v=sS[ic*PSZ+(r+dy)*PW+c+dx];
        int k=(ic*9+dy*3+dx)*8;
        const float4* qu=(const float4*)(sWu+k);
        const float4* qr=(const float4*)(sWr+k);
        float4 a=qu[0],bq=qu[1],cq=qr[0],dq=qr[1];
        au[0]=fmaf(v,a.x,au[0]);au[1]=fmaf(v,a.y,au[1]);au[2]=fmaf(v,a.z,au[2]);au[3]=fmaf(v,a.w,au[3]);
        au[4]=fmaf(v,bq.x,au[4]);au[5]=fmaf(v,bq.y,au[5]);au[6]=fmaf(v,bq.z,au[6]);au[7]=fmaf(v,bq.w,au[7]);
        ar[0]=fmaf(v,cq.x,ar[0]);ar[1]=fmaf(v,cq.y,ar[1]);ar[2]=fmaf(v,cq.z,ar[2]);ar[3]=fmaf(v,cq.w,ar[3]);
        ar[4]=fmaf(v,dq.x,ar[4]);ar[5]=fmaf(v,dq.y,ar[5]);ar[6]=fmaf(v,dq.z,ar[6]);ar[7]=fmaf(v,dq.w,ar[7]);
      }
#pragma unroll
    for(int o=0;o<8;o++){
      upd[o]=1.f/(1.f+__expf(-au[o]));
      float rst=1.f/(1.f+__expf(-ar[o]));
      pr[o]=sS[(4+o)*PSZ+(r+1)*PW+c+1];
      rp[o]=pr[o]*rst;}
  }
  __syncthreads();
  if(t<HWp)
#pragma unroll
    for(int o=0;o<8;o++)sS[(4+o)*PSZ+(r+1)*PW+c+1]=rp[o];
  __syncthreads();
  if(t>=HWp)return;
  float ao[8];
#pragma unroll
  for(int o=0;o<8;o++)ao[o]=__ldg(&ob[o]);
  for(int ic=0;ic<12;ic++)
#pragma unroll
    for(int dy=0;dy<3;dy++)
#pragma unroll
    for(int dx=0;dx<3;dx++){
      float v=sS[ic*PSZ+(r+dy)*PW+c+dx];
      int k=(ic*9+dy*3+dx)*8;
      const float4* q=(const float4*)(sWo+k);
      float4 a=q[0],bq=q[1];
      ao[0]=fmaf(v,a.x,ao[0]);ao[1]=fmaf(v,a.y,ao[1]);ao[2]=fmaf(v,a.z,ao[2]);ao[3]=fmaf(v,a.w,ao[3]);
      ao[4]=fmaf(v,bq.x,ao[4]);ao[5]=fmaf(v,bq.y,ao[5]);ao[6]=fmaf(v,bq.z,ao[6]);ao[7]=fmaf(v,bq.w,ao[7]);}
#pragma unroll
  for(int o=0;o<8;o++){
    float ov=tanhf(ao[o]);
    float sn=pr[o]*(1.f-upd[o])+ov*upd[o];
    out[(size_t)n*9*HWp+(o+1)*HWp+t]=sn;}
}

extern "C" void kernel_launch(void* const* d_in, const int* in_sizes, int n_in,
                              void* d_out, int out_size) {
  const float* cv  =(const float*)d_in[0];
  const float* sp  =(const float*)d_in[1];
  const float* dimp=(const float*)d_in[2];
  float* out=(float*)d_out;
  cudaFuncSetAttribute(rc2_k,cudaFuncAttributeMaxDynamicSharedMemorySize,64*PSZ*4+9216*4);
  cudaFuncSetAttribute(rc3_k,cudaFuncAttributeMaxDynamicSharedMemorySize,32*PSZ*4);

  zstats_k<<<16,256>>>();
  // stage A (cv1)
  stats1_k<<<NIMG,256>>>(cv,(const float*)d_in[3],0);
  bnfin_k<<<1,8>>>(0,(const float*)d_in[5],(const float*)d_in[6],8);
  pass2_k<<<NIMG,256>>>(cv,(const float*)d_in[3],(const float*)d_in[7],0,0,1,0);
  bnfin_k<<<1,8>>>(1,(const float*)d_in[9],(const float*)d_in[10],1);
  // per-image softmax + fused stage-B conv1 stats
  smaxi_k<<<NIMG,256>>>((const float*)d_in[11]);
  bnfin_k<<<1,8>>>(2,(const float*)d_in[13],(const float*)d_in[14],8);
  // stage B (cv2)
  pass2_k<<<NIMG,256>>>(cv,(const float*)d_in[11],(const float*)d_in[15],1,2,3,1);
  bnfin_k<<<1,8>>>(3,(const float*)d_in[17],(const float*)d_in[18],1);
  // softmax over positions + conf + propagation
  sprop_k<<<NB,512>>>(sp);
  // response head
  rc1_k<<<dim3(NB,2),512>>>(dimp,(const float*)d_in[19],(const float*)d_in[20]);
  rc2_k<<<dim3(NB,2),352,64*PSZ*4+9216*4>>>((const float*)d_in[21],(const float*)d_in[22]);
  rc3_k<<<NB,512,32*PSZ*4>>>((const float*)d_in[23],(const float*)d_in[24],out);
  // GRU
  pool_k<<<NB,256>>>(dimp);
  gru_k<<<NB,512>>>(dimp,
    (const float*)d_in[25],(const float*)d_in[26],
    (const float*)d_in[27],(const float*)d_in[28],
    (const float*)d_in[29],(const float*)d_in[30],out);
}

// round 17
// speedup vs baseline: 1.2710x; 1.0989x over previous
#include <cuda_runtime.h>
#include <math.h>

#define NB 64
#define HWp 484
#define NIMG (NB*HWp)
#define PW 24
#define SSZ 600
#define NS 64
#define SOFF(r) ((r)*PW + ((r)>>1))

__constant__ float c_w[288];   // [0:72)=cv1_w1 [72:144)=cv1_w2 [144:216)=cv2_w1 [216:288)=cv2_w2

__device__ float g_z[(size_t)NIMG*HWp];
__device__ float g_z2[(size_t)NIMG*HWp];
__device__ float g_prop[NB*8*HWp];
__device__ float g_conf[NB*HWp];
__device__ float g_fused[NB*HWp];
__device__ float g_r1[(size_t)NB*64*HWp];
__device__ float g_r2[(size_t)NB*32*HWp];
__device__ float g_st[4][16*NS];
__device__ float g_sc[4][8], g_sh[4][8];
__device__ float g_pool[NB*2];

__device__ __forceinline__ float wsum(float v){
#pragma unroll
  for(int o=16;o;o>>=1) v+=__shfl_xor_sync(~0u,v,o);
  return v;
}
__device__ __forceinline__ float wmax(float v){
#pragma unroll
  for(int o=16;o;o>>=1) v=fmaxf(v,__shfl_xor_sync(~0u,v,o));
  return v;
}

// 3x4 patch from swizzled buffer, scalar loads
__device__ __forceinline__ void ldp12s(const float* __restrict__ s,int r,int cp,float v[12]){
#pragma unroll
  for(int dy=0;dy<3;dy++){
    const float* p=s+SOFF(r+dy)+cp;
#pragma unroll
    for(int dx=0;dx<4;dx++)v[dy*4+dx]=p[dx];
  }
}
// 4x4 patch, scalar loads
__device__ __forceinline__ void ldp16s(const float* __restrict__ s,int r0,int c0,float v[16]){
#pragma unroll
  for(int dy=0;dy<4;dy++){
    const float* p=s+SOFF(r0+dy)+c0;
#pragma unroll
    for(int dx=0;dx<4;dx++)v[dy*4+dx]=p[dx];
  }
}
// 3x3 conv -> 1x2, weights from constant memory at offset wo
__device__ __forceinline__ void c3x3_2c(const float v[12],int wo,float&a0,float&a1){
#pragma unroll
  for(int ky=0;ky<3;ky++)
#pragma unroll
  for(int kx=0;kx<3;kx++){
    float wv=c_w[wo+ky*3+kx];
    a0=fmaf(wv,v[ky*4+kx],a0); a1=fmaf(wv,v[ky*4+kx+1],a1);
  }
}
// 3x3 conv -> 2x2, constant weights
__device__ __forceinline__ void c3x3_4c(const float v[16],int wo,
    float&a00,float&a01,float&a10,float&a11){
#pragma unroll
  for(int ky=0;ky<3;ky++)
#pragma unroll
  for(int kx=0;kx<3;kx++){
    float wv=c_w[wo+ky*3+kx];
    a00=fmaf(wv,v[ky*4+kx],a00);      a01=fmaf(wv,v[ky*4+kx+1],a01);
    a10=fmaf(wv,v[(ky+1)*4+kx],a10);  a11=fmaf(wv,v[(ky+1)*4+kx+1],a11);
  }
}

__global__ void zstats_k(){
  int i=blockIdx.x*256+threadIdx.x;
  if(i<4*16*NS)((float*)g_st)[i]=0.f;
}

// conv(1->8) per image, per-channel sum/sumsq (1x2 tiles, constant weights)
__global__ __launch_bounds__(256) void stats1_k(const float* __restrict__ in,
    int wo,int stage){
  __shared__ float sI[SSZ],sA[16];
  int img=blockIdx.x,t=threadIdx.x;
  const float* src=in+(size_t)img*HWp;
  for(int i=t;i<576;i+=256){int r=i/PW,c=i-r*PW;
    sI[SOFF(r)+c]=(r>=1&&r<=22&&c>=1&&c<=22)?src[(r-1)*22+c-1]:0.f;}
  if(t<16)sA[t]=0.f;
  __syncthreads();
  float ls[8],lq[8];
#pragma unroll
  for(int o=0;o<8;o++){ls[o]=0.f;lq[o]=0.f;}
  if(t<242){
    int r=t/11,cp=(t-r*11)*2;
    float v[12]; ldp12s(sI,r,cp,v);
#pragma unroll
    for(int oc=0;oc<8;oc++){
      float a=0.f,b=0.f;
      c3x3_2c(v,wo+oc*9,a,b);
      ls[oc]=a+b; lq[oc]=a*a+b*b;
    }
  }
#pragma unroll
  for(int o=0;o<8;o++){
    float s=wsum(ls[o]),q=wsum(lq[o]);
    if((t&31)==0){atomicAdd(&sA[o],s);atomicAdd(&sA[8+o],q);}}
  __syncthreads();
  if(t<16)atomicAdd(&g_st[stage][t*NS+(img&(NS-1))],sA[t]);
}

__global__ void bnfin_k(int stage,const float* __restrict__ g,
    const float* __restrict__ be,int nch){
  int c=threadIdx.x; if(c>=nch)return;
  float S=0.f,Q=0.f;
  for(int i=0;i<NS;i++){S+=g_st[stage][c*NS+i];Q+=g_st[stage][(8+c)*NS+i];}
  float inv=1.f/((float)NIMG*(float)HWp),m=S*inv,v=fmaxf(Q*inv-m*m,0.f);
  float sc=g[c]*rsqrtf(v+1e-5f);
  g_sc[stage][c]=sc; g_sh[stage][c]=be[c]-m*sc;
}

// conv1(1x2)+BN+ReLU in swizzled SMEM -> conv2 ic-split 2x2 -> z + stats (constant weights)
__global__ __launch_bounds__(256) void pass2_k(const float* __restrict__ in,
    int wo1,int wo2,int insel,int bnst,int stst,int zsel){
  __shared__ float sI[SSZ],sY[8*SSZ],sB[16],sA[2];
  __shared__ __align__(16) float zP[484];
  int img=blockIdx.x,t=threadIdx.x;
  const float* src=(insel?(const float*)g_z:in)+(size_t)img*HWp;
  for(int i=t;i<576;i+=256){int r=i/PW,c=i-r*PW;
    sI[SOFF(r)+c]=(r>=1&&r<=22&&c>=1&&c<=22)?src[(r-1)*22+c-1]:0.f;}
  for(int i=t;i<736;i+=256){
    int ch=i/92,j=i-ch*92,off;
    if(j<24)off=SOFF(0)+j;
    else if(j<48)off=SOFF(23)+(j-24);
    else if(j<70)off=SOFF(j-47);
    else off=SOFF(j-69)+23;
    sY[ch*SSZ+off]=0.f;
  }
  if(t<8){sB[t]=g_sc[bnst][t];sB[8+t]=g_sh[bnst][t];}
  if(t<2)sA[t]=0.f;
  __syncthreads();
  // conv1: 242 threads, 1x2 tiles
  if(t<242){
    int r=t/11,cp=(t-r*11)*2;
    float v[12]; ldp12s(sI,r,cp,v);
#pragma unroll
    for(int oc=0;oc<8;oc++){
      float a=0.f,b=0.f;
      c3x3_2c(v,wo1+oc*9,a,b);
      float sc=sB[oc],sh=sB[8+oc];
      float* yp=sY+oc*SSZ+SOFF(r+1)+cp+1;
      yp[0]=fmaxf(fmaf(a,sc,sh),0.f);
      yp[1]=fmaxf(fmaf(b,sc,sh),0.f);
    }
  }
  __syncthreads();
  // conv2: ic-split across block halves, 2x2 tiles
  int g=t>>7, idx=t&127;
  bool act=idx<121;
  float z00=0.f,z01=0.f,z10=0.f,z11=0.f;
  int r0=0,c0=0;
  if(act){
    r0=(idx/11)*2; c0=(idx%11)*2;
#pragma unroll
    for(int ic4=0;ic4<4;ic4++){
      float u[16]; ldp16s(sY+(g*4+ic4)*SSZ,r0,c0,u);
      c3x3_4c(u,wo2+(g*4+ic4)*9,z00,z01,z10,z11);
    }
  }
  if(g==1&&act){
    *(float4*)&zP[idx*4]=make_float4(z00,z01,z10,z11);
  }
  __syncthreads();
  float ls=0.f,lq=0.f;
  if(g==0&&act){
    float4 q=*(const float4*)&zP[idx*4];
    z00+=q.x;z01+=q.y;z10+=q.z;z11+=q.w;
    float* zo=(zsel?g_z2:g_z)+(size_t)img*HWp+r0*22+c0;
    *(float2*)zo=make_float2(z00,z01);
    *(float2*)(zo+22)=make_float2(z10,z11);
    ls=z00+z01+z10+z11;
    lq=z00*z00+z01*z01+z10*z10+z11*z11;
  }
  float s=wsum(ls),q=wsum(lq);
  if((t&31)==0&&t<128){atomicAdd(&sA[0],s);atomicAdd(&sA[1],q);}
  __syncthreads();
  if(t<2)atomicAdd(&g_st[stst][t*8*NS+(img&(NS-1))],sA[t]);
}

// per-image softmax + fused stage-B conv1 stats (constant weights, wo=144)
__global__ __launch_bounds__(256) void smaxi_k(){
  __shared__ float sP[SSZ],red[9],sA[16];
  size_t base=(size_t)blockIdx.x*HWp;
  int t=threadIdx.x;
  if(t<92){
    int j=t,off;
    if(j<24)off=SOFF(0)+j;
    else if(j<48)off=SOFF(23)+(j-24);
    else if(j<70)off=SOFF(j-47);
    else off=SOFF(j-69)+23;
    sP[off]=0.f;
  }
  if(t<16)sA[t]=0.f;
  float sc=g_sc[1][0];
  float v0=(t<HWp)?g_z[base+t]*sc:-1e30f;
  float v1=(t+256<HWp)?g_z[base+t+256]*sc:-1e30f;
  float m=wmax(fmaxf(v0,v1));
  if((t&31)==0)red[t>>5]=m;
  __syncthreads();
  if(t==0){float x=red[0];for(int i=1;i<8;i++)x=fmaxf(x,red[i]);red[8]=x;}
  __syncthreads();
  m=red[8];
  float e0=(t<HWp)?__expf(v0-m):0.f;
  float e1=(t+256<HWp)?__expf(v1-m):0.f;
  float s=wsum(e0+e1);
  __syncthreads();
  if((t&31)==0)red[t>>5]=s;
  __syncthreads();
  if(t==0){float x=0.f;for(int i=0;i<8;i++)x+=red[i];red[8]=x;}
  __syncthreads();
  float inv=1.f/red[8];
  float p0=e0*inv,p1=e1*inv;
  if(t<HWp){g_z[base+t]=p0;int r=t/22,c=t-r*22;sP[SOFF(r+1)+c+1]=p0;}
  if(t+256<HWp){g_z[base+t+256]=p1;int i2=t+256,r=i2/22,c=i2-r*22;sP[SOFF(r+1)+c+1]=p1;}
  __syncthreads();
  float ls[8],lq[8];
#pragma unroll
  for(int o=0;o<8;o++){ls[o]=0.f;lq[o]=0.f;}
  if(t<242){
    int r=t/11,cp=(t-r*11)*2;
    float v[12]; ldp12s(sP,r,cp,v);
#pragma unroll
    for(int oc=0;oc<8;oc++){
      float a=0.f,b=0.f;
      c3x3_2c(v,144+oc*9,a,b);
      ls[oc]=a+b; lq[oc]=a*a+b*b;
    }
  }
#pragma unroll
  for(int o=0;o<8;o++){
    float su=wsum(ls[o]),q=wsum(lq[o]);
    if((t&31)==0){atomicAdd(&sA[o],su);atomicAdd(&sA[8+o],q);}}
  __syncthreads();
  if(t<16)atomicAdd(&g_st[2][t*NS+(blockIdx.x&(NS-1))],sA[t]);
}

// two-pass softmax over source positions + conf + einsum prop (coalesced)
__global__ __launch_bounds__(512) void sprop_k(const float* __restrict__ sp){
  __shared__ float sS[HWp*8];
  int n=blockIdx.x,t=threadIdx.x;
  for(int i=t;i<HWp*8;i+=512){int d=i/HWp,p=i-d*HWp;sS[p*8+d]=sp[(n*8+d)*HWp+p];}
  __syncthreads();
  if(t>=HWp)return;
  float sc=g_sc[3][0];
  const float* z=g_z2+(size_t)n*HWp*HWp+t;
  float m=-1e30f;
  for(int p=0;p<HWp;p++)m=fmaxf(m,__ldg(z+(size_t)p*HWp)*sc);
  float s=0.f,acc[8];
#pragma unroll
  for(int d=0;d<8;d++)acc[d]=0.f;
  for(int p=0;p<HWp;p++){
    float e=__expf(__ldg(z+(size_t)p*HWp)*sc-m);
    s+=e;
    const float* st=&sS[p*8];
#pragma unroll
    for(int d=0;d<8;d++)acc[d]=fmaf(e,st[d],acc[d]);
  }
  float inv=1.f/s;
  g_conf[n*HWp+t]=inv;
#pragma unroll
  for(int d=0;d<8;d++)g_prop[(n*8+d)*HWp+t]=acc[d]*inv;
}

// conv 10->64 (+bias,ReLU), 32 oc per block (grid.y=2)
#define PSZ 576
__global__ __launch_bounds__(512) void rc1_k(const float* __restrict__ dimp,
    const float* __restrict__ w,const float* __restrict__ b){
  __shared__ float sI[10*PSZ];
  __shared__ float4 sW4[10*9*8];
  int n=blockIdx.x,o0=blockIdx.y*32,t=threadIdx.x;
  for(int i=t;i<10*PSZ;i+=512){
    int ch=i/PSZ,j=i-ch*PSZ,r=j/PW,c=j-r*PW;float val=0.f;
    if(r>=1&&r<=22&&c>=1&&c<=22){int px=(r-1)*22+c-1;
      val=(ch<8)?g_prop[(n*8+ch)*HWp+px]:((ch==8)?dimp[n*HWp+px]:g_conf[n*HWp+px]);}
    sI[i]=val;}
  for(int i=t;i<2880;i+=512)((float*)sW4)[i]=w[(o0+(i&31))*90+(i>>5)];
  __syncthreads();
  if(t>=HWp)return;
  int r=t/22,c=t-r*22;
  float acc[32];
#pragma unroll
  for(int o=0;o<32;o++)acc[o]=__ldg(&b[o0+o]);
  for(int ic=0;ic<10;ic++){
    float v[9];
#pragma unroll
    for(int dy=0;dy<3;dy++)
#pragma unroll
    for(int dx=0;dx<3;dx++)v[dy*3+dx]=sI[ic*PSZ+(r+dy)*PW+c+dx];
#pragma unroll
    for(int k=0;k<9;k++){
      float tv=v[k];
#pragma unroll
      for(int o4=0;o4<8;o4++){
        float4 wq=sW4[(ic*9+k)*8+o4];
        acc[o4*4+0]=fmaf(tv,wq.x,acc[o4*4+0]);acc[o4*4+1]=fmaf(tv,wq.y,acc[o4*4+1]);
        acc[o4*4+2]=fmaf(tv,wq.z,acc[o4*4+2]);acc[o4*4+3]=fmaf(tv,wq.w,acc[o4*4+3]);}
    }
  }
#pragma unroll
  for(int o=0;o<32;o++)g_r1[((size_t)n*64+o0+o)*HWp+t]=fmaxf(acc[o],0.f);
}

// conv 64->32 (+bias,ReLU), row x oc thread map, 16 oc per block (grid.y=2)
__global__ __launch_bounds__(352) void rc2_k(const float* __restrict__ w,
    const float* __restrict__ b){
  extern __shared__ float sm[];
  float* sW=sm+64*PSZ;
  int n=blockIdx.x,o0=blockIdx.y*16,t=threadIdx.x;
  for(int i=t;i<64*PSZ;i+=352){
    int ch=i/PSZ,j=i-ch*PSZ,r=j/PW,c=j-r*PW;
    sm[i]=(r>=1&&r<=22&&c>=1&&c<=22)?g_r1[((size_t)n*64+ch)*HWp+(r-1)*22+c-1]:0.f;}
  for(int i=t;i<9216;i+=352)sW[i]=w[(o0+(i&15))*576+(i>>4)];
  __syncthreads();
  int row=t>>4,ocl=t&15;
  if(row>=22)return;
  float acc[22];
  float bias=__ldg(&b[o0+ocl]);
#pragma unroll
  for(int c=0;c<22;c++)acc[c]=bias;
  for(int ic=0;ic<64;ic++){
    const float* pb=sm+ic*PSZ+row*PW;
    const float* pw=sW+ic*144+ocl;
#pragma unroll
    for(int dy=0;dy<3;dy++){
      float v[24];
      const float4* q=(const float4*)(pb+dy*PW);
#pragma unroll
      for(int j=0;j<6;j++){float4 f=q[j];v[j*4]=f.x;v[j*4+1]=f.y;v[j*4+2]=f.z;v[j*4+3]=f.w;}
#pragma unroll
      for(int kx=0;kx<3;kx++){
        float wv=pw[(dy*3+kx)*16];
#pragma unroll
        for(int c=0;c<22;c++)acc[c]=fmaf(wv,v[c+kx],acc[c]);}
    }
  }
#pragma unroll
  for(int c=0;c<22;c++)
    g_r2[((size_t)n*32+o0+ocl)*HWp+row*22+c]=fmaxf(acc[c],0.f);
}

// conv 32->1 + sigmoid -> fused (output channel 0)
__global__ __launch_bounds__(512) void rc3_k(const float* __restrict__ w,
    const float* __restrict__ b,float* __restrict__ out){
  extern __shared__ float sm[];
  __shared__ float sW[288];
  int n=blockIdx.x,t=threadIdx.x;
  for(int i=t;i<32*PSZ;i+=512){
    int ch=i/PSZ,j=i-ch*PSZ,r=j/PW,c=j-r*PW;
    sm[i]=(r>=1&&r<=22&&c>=1&&c<=22)?g_r2[((size_t)n*32+ch)*HWp+(r-1)*22+c-1]:0.f;}
  if(t<288)sW[t]=w[t];
  __syncthreads();
  if(t>=HWp)return;
  int r=t/22,c=t-r*22;
  float a=__ldg(&b[0]);
  for(int ic=0;ic<32;ic++)
#pragma unroll
    for(int dy=0;dy<3;dy++)
#pragma unroll
    for(int dx=0;dx<3;dx++)
      a=fmaf(sW[ic*9+dy*3+dx],sm[ic*PSZ+(r+dy)*PW+c+dx],a);
  float f=1.f/(1.f+__expf(-a));
  g_fused[n*HWp+t]=f;
  out[(size_t)n*9*HWp+t]=f;
}

__global__ __launch_bounds__(256) void pool_k(const float* __restrict__ dimp){
  __shared__ float red[16];
  int n=blockIdx.x,t=threadIdx.x;
  float m0=-1e30f,m1=-1e30f;
  for(int i=t;i<HWp;i+=256){
    m0=fmaxf(m0,dimp[n*HWp+i]);
    m1=fmaxf(m1,g_fused[n*HWp+i]);}
  m0=wmax(m0);m1=wmax(m1);
  if((t&31)==0){red[t>>5]=m0;red[8+(t>>5)]=m1;}
  __syncthreads();
  if(t==0){
    float a=red[0],b=red[8];
    for(int i=1;i<8;i++){a=fmaxf(a,red[i]);b=fmaxf(b,red[8+i]);}
    g_pool[n*2]=a;g_pool[n*2+1]=b;}
}

// fused ConvGRU
__global__ __launch_bounds__(512) void gru_k(const float* __restrict__ dimp,
    const float* __restrict__ rw,const float* __restrict__ rb,
    const float* __restrict__ uw,const float* __restrict__ ub,
    const float* __restrict__ ow,const float* __restrict__ ob,
    float* __restrict__ out){
  __shared__ float sS[12*PSZ];
  __shared__ __align__(16) float sWu[864];
  __shared__ __align__(16) float sWr[864];
  __shared__ __align__(16) float sWo[864];
  int n=blockIdx.x,t=threadIdx.x;
  float p0=g_pool[n*2],p1=g_pool[n*2+1];
  for(int i=t;i<12*PSZ;i+=512){
    int ch=i/PSZ,j=i-ch*PSZ,r=j/PW,c=j-r*PW;float val=0.f;
    if(r>=1&&r<=22&&c>=1&&c<=22){int px=(r-1)*22+c-1;
      val=(ch==0)?dimp[n*HWp+px]:(ch==1)?g_fused[n*HWp+px]:
          (ch==2)?p0:(ch==3)?p1:g_prop[(n*8+ch-4)*HWp+px];}
    sS[i]=val;}
  for(int i=t;i<864;i+=512){
    int oc=i&7,rest=i>>3;
    sWu[i]=uw[oc*108+rest];sWr[i]=rw[oc*108+rest];sWo[i]=ow[oc*108+rest];}
  __syncthreads();
  int r=t/22,c=t-r*22;
  float upd[8],pr[8],rp[8];
  if(t<HWp){
    float au[8],ar[8];
#pragma unroll
    for(int o=0;o<8;o++){au[o]=__ldg(&ub[o]);ar[o]=__ldg(&rb[o]);}
    for(int ic=0;ic<12;ic++)
#pragma unroll
      for(int dy=0;dy<3;dy++)
#pragma unroll
      for(int dx=0;dx<3;dx++){
        float v=sS[ic*PSZ+(r+dy)*PW+c+dx];
        int k=(ic*9+dy*3+dx)*8;
        const float4* qu=(const float4*)(sWu+k);
        const float4* qr=(const float4*)(sWr+k);
        float4 a=qu[0],bq=qu[1],cq=qr[0],dq=qr[1];
        au[0]=fmaf(v,a.x,au[0]);au[1]=fmaf(v,a.y,au[1]);au[2]=fmaf(v,a.z,au[2]);au[3]=fmaf(v,a.w,au[3]);
        au[4]=fmaf(v,bq.x,au[4]);au[5]=fmaf(v,bq.y,au[5]);au[6]=fmaf(v,bq.z,au[6]);au[7]=fmaf(v,bq.w,au[7]);
        ar[0]=fmaf(v,cq.x,ar[0]);ar[1]=fmaf(v,cq.y,ar[1]);ar[2]=fmaf(v,cq.z,ar[2]);ar[3]=fmaf(v,cq.w,ar[3]);
        ar[4]=fmaf(v,dq.x,ar[4]);ar[5]=fmaf(v,dq.y,ar[5]);ar[6]=fmaf(v,dq.z,ar[6]);ar[7]=fmaf(v,dq.w,ar[7]);
      }
#pragma unroll
    for(int o=0;o<8;o++){
      upd[o]=1.f/(1.f+__expf(-au[o]));
      float rst=1.f/(1.f+__expf(-ar[o]));
      pr[o]=sS[(4+o)*PSZ+(r+1)*PW+c+1];
      rp[o]=pr[o]*rst;}
  }
  __syncthreads();
  if(t<HWp)
#pragma unroll
    for(int o=0;o<8;o++)sS[(4+o)*PSZ+(r+1)*PW+c+1]=rp[o];
  __syncthreads();
  if(t>=HWp)return;
  float ao[8];
#pragma unroll
  for(int o=0;o<8;o++)ao[o]=__ldg(&ob[o]);
  for(int ic=0;ic<12;ic++)
#pragma unroll
    for(int dy=0;dy<3;dy++)
#pragma unroll
    for(int dx=0;dx<3;dx++){
      float v=sS[ic*PSZ+(r+dy)*PW+c+dx];
      int k=(ic*9+dy*3+dx)*8;
      const float4* q=(const float4*)(sWo+k);
      float4 a=q[0],bq=q[1];
      ao[0]=fmaf(v,a.x,ao[0]);ao[1]=fmaf(v,a.y,ao[1]);ao[2]=fmaf(v,a.z,ao[2]);ao[3]=fmaf(v,a.w,ao[3]);
      ao[4]=fmaf(v,bq.x,ao[4]);ao[5]=fmaf(v,bq.y,ao[5]);ao[6]=fmaf(v,bq.z,ao[6]);ao[7]=fmaf(v,bq.w,ao[7]);}
#pragma unroll
  for(int o=0;o<8;o++){
    float ov=tanhf(ao[o]);
    float sn=pr[o]*(1.f-upd[o])+ov*upd[o];
    out[(size_t)n*9*HWp+(o+1)*HWp+t]=sn;}
}

extern "C" void kernel_launch(void* const* d_in, const int* in_sizes, int n_in,
                              void* d_out, int out_size) {
  const float* cv  =(const float*)d_in[0];
  const float* sp  =(const float*)d_in[1];
  const float* dimp=(const float*)d_in[2];
  float* out=(float*)d_out;
  cudaFuncSetAttribute(rc2_k,cudaFuncAttributeMaxDynamicSharedMemorySize,64*PSZ*4+9216*4);
  cudaFuncSetAttribute(rc3_k,cudaFuncAttributeMaxDynamicSharedMemorySize,32*PSZ*4);

  // cv conv weights -> constant memory (D2D memcpy nodes, graph-capturable)
  cudaMemcpyToSymbolAsync(c_w,d_in[3], 72*4,  0*4,cudaMemcpyDeviceToDevice,0);
  cudaMemcpyToSymbolAsync(c_w,d_in[7], 72*4, 72*4,cudaMemcpyDeviceToDevice,0);
  cudaMemcpyToSymbolAsync(c_w,d_in[11],72*4,144*4,cudaMemcpyDeviceToDevice,0);
  cudaMemcpyToSymbolAsync(c_w,d_in[15],72*4,216*4,cudaMemcpyDeviceToDevice,0);

  zstats_k<<<16,256>>>();
  // stage A (cv1)
  stats1_k<<<NIMG,256>>>(cv,0,0);
  bnfin_k<<<1,8>>>(0,(const float*)d_in[5],(const float*)d_in[6],8);
  pass2_k<<<NIMG,256>>>(cv,0,72,0,0,1,0);
  bnfin_k<<<1,8>>>(1,(const float*)d_in[9],(const float*)d_in[10],1);
  // per-image softmax + fused stage-B conv1 stats
  smaxi_k<<<NIMG,256>>>();
  bnfin_k<<<1,8>>>(2,(const float*)d_in[13],(const float*)d_in[14],8);
  // stage B (cv2)
  pass2_k<<<NIMG,256>>>(cv,144,216,1,2,3,1);
  bnfin_k<<<1,8>>>(3,(const float*)d_in[17],(const float*)d_in[18],1);
  // softmax over positions + conf + propagation
  sprop_k<<<NB,512>>>(sp);
  // response head
  rc1_k<<<dim3(NB,2),512>>>(dimp,(const float*)d_in[19],(const float*)d_in[20]);
  rc2_k<<<dim3(NB,2),352,64*PSZ*4+9216*4>>>((const float*)d_in[21],(const float*)d_in[22]);
  rc3_k<<<NB,512,32*PSZ*4>>>((const float*)d_in[23],(const float*)d_in[24],out);
  // GRU
  pool_k<<<NB,256>>>(dimp);
  gru_k<<<NB,512>>>(dimp,
    (const float*)d_in[25],(const float*)d_in[26],
    (const float*)d_in[27],(const float*)d_in[28],
    (const float*)d_in[29],(const float*)d_in[30],out);
}